// round 4
// baseline (speedup 1.0000x reference)
#include <cuda_runtime.h>
#include <math.h>

typedef unsigned long long u64;
typedef unsigned int u32;

#define NWARP 4
#define TLB   8        // 2 TLs per warp
#define BUF   2176     // per-warp scratch floats (t=1 regions offset by 16 floats to dodge bank overlap)

__device__ __forceinline__ u64 pk2(float a, float b) {
    u64 r; asm("mov.b64 %0, {%1, %2};" : "=l"(r) : "r"(__float_as_uint(a)), "r"(__float_as_uint(b)));
    return r;
}
__device__ __forceinline__ void upk2(u64 v, float& a, float& b) {
    u32 x, y; asm("mov.b64 {%0, %1}, %2;" : "=r"(x), "=r"(y) : "l"(v));
    a = __uint_as_float(x); b = __uint_as_float(y);
}
__device__ __forceinline__ u64 dup2(float a) { return pk2(a, a); }
__device__ __forceinline__ u64 ffma2(u64 a, u64 b, u64 c) {
    u64 d; asm("fma.rn.f32x2 %0, %1, %2, %3;" : "=l"(d) : "l"(a), "l"(b), "l"(c)); return d;
}
__device__ __forceinline__ u64 add2(u64 a, u64 b) {
    u64 d; asm("add.rn.f32x2 %0, %1, %2;" : "=l"(d) : "l"(a), "l"(b)); return d;
}
__device__ __forceinline__ float2 relu2(u64 v) {
    float a, b; upk2(v, a, b); return make_float2(fmaxf(a, 0.f), fmaxf(b, 0.f));
}
__device__ __forceinline__ ulonglong2 ld128(const float* p) { return *reinterpret_cast<const ulonglong2*>(p); }
__device__ __forceinline__ float4 ld4(const float* p)       { return *reinterpret_cast<const float4*>(p); }
__device__ __forceinline__ void st4(float* p, float4 v)     { *reinterpret_cast<float4*>(p) = v; }

// Per-warp scratch A[BUF] regions (floats):
//   h    : t*528 + l*128 + j        [0,1056)
//   emb  : 1600 + t*272 + l*64 + j  [1600,2144)
//   qkv  : t*784 + l*192 + m*64 + j [0,1568)    (h dead)
//   o    : t*272 + l*64 + j         [0,544)     (qkv reads done)
//   obar : 1088 + t*80 + j          (in dead qkv t=1)
//   ph   : 1280 + t*144 + j         (in dead qkv t=1)

__global__ __launch_bounds__(NWARP * 32)
void policy_kernel(
    const float* __restrict__ queue, const float* __restrict__ waiting,
    const float* __restrict__ phase_onehot, const float* __restrict__ elapsed,
    const int*   __restrict__ region_ids, const float* __restrict__ noise,
    const float* __restrict__ lane_w1, const float* __restrict__ lane_b1,
    const float* __restrict__ lane_w2, const float* __restrict__ lane_b2,
    const float* __restrict__ attn_in_w, const float* __restrict__ attn_in_b,
    const float* __restrict__ attn_out_w, const float* __restrict__ attn_out_b,
    const float* __restrict__ phase_w1, const float* __restrict__ phase_b1,
    const float* __restrict__ phase_w2, const float* __restrict__ phase_b2,
    const float* __restrict__ region_table,
    const float* __restrict__ head_w1, const float* __restrict__ head_b1,
    const float* __restrict__ head_w2, const float* __restrict__ head_b2,
    const float* __restrict__ log_std,
    float* __restrict__ out, int N)
{
    __shared__ float wb[NWARP][BUF];
    __shared__ float featp[200][12];      // transposed features, rows 0..7 (stride 12: 8B-aligned pairs)
    __shared__ float partial[NWARP][8];

    const int tid  = threadIdx.x;
    const int warp = tid >> 5, lane = tid & 31;
    const int n0   = blockIdx.x * TLB + warp * 2;
    float* A = wb[warp];

    const int rgt = lane >> 4;            // half-warp: which of the warp's 2 TLs
    const int jg4 = (lane & 15) * 4;      // 4-wide j slice in [0,64)
    const int j4  = lane * 4;             // 4-wide j slice in [0,128)

    const int na = min(n0,     N - 1);
    const int nb = min(n0 + 1, N - 1);
    const float ee[2] = { elapsed[na], elapsed[nb] };

    // ---- Stage 1: lane MLP L1 -> h[t][l][128] ----
    {
        ulonglong2 W0 = ld128(lane_w1 + j4);
        ulonglong2 W1 = ld128(lane_w1 + 128 + j4);
        ulonglong2 W2 = ld128(lane_w1 + 256 + j4);
        ulonglong2 BB = ld128(lane_b1 + j4);
#pragma unroll
        for (int t = 0; t < 2; t++) {
            const int n = t ? nb : na;
            float4 qv = ld4(queue + 4 * n);
            float4 wv = ld4(waiting + 4 * n);
            u64 ed = dup2(ee[t]);
            float qa[4] = {qv.x, qv.y, qv.z, qv.w};
            float wa[4] = {wv.x, wv.y, wv.z, wv.w};
#pragma unroll
            for (int l = 0; l < 4; l++) {
                u64 qd = dup2(qa[l]), wd = dup2(wa[l]);
                u64 lo = ffma2(qd, W0.x, BB.x); lo = ffma2(wd, W1.x, lo); lo = ffma2(ed, W2.x, lo);
                u64 hi = ffma2(qd, W0.y, BB.y); hi = ffma2(wd, W1.y, hi); hi = ffma2(ed, W2.y, hi);
                float2 r0 = relu2(lo), r1 = relu2(hi);
                st4(A + t * 528 + l * 128 + j4, make_float4(r0.x, r0.y, r1.x, r1.y));
            }
        }
    }
    __syncwarp();

    // ---- Stage 2: lane MLP L2 -> emb[t][l][64] (half-warp per TL, weight dedup) ----
    {
        ulonglong2 bb = ld128(lane_b2 + jg4);
        u64 acc[4][2];
#pragma unroll
        for (int l = 0; l < 4; l++) { acc[l][0] = bb.x; acc[l][1] = bb.y; }
#pragma unroll 2
        for (int k = 0; k < 128; k += 4) {
            float hv[4][4];
#pragma unroll
            for (int l = 0; l < 4; l++) {
                float4 v = ld4(A + rgt * 528 + l * 128 + k);
                hv[l][0] = v.x; hv[l][1] = v.y; hv[l][2] = v.z; hv[l][3] = v.w;
            }
#pragma unroll
            for (int kk = 0; kk < 4; kk++) {
                ulonglong2 w = ld128(lane_w2 + (k + kk) * 64 + jg4);
#pragma unroll
                for (int l = 0; l < 4; l++) {
                    u64 d = dup2(hv[l][kk]);
                    acc[l][0] = ffma2(d, w.x, acc[l][0]);
                    acc[l][1] = ffma2(d, w.y, acc[l][1]);
                }
            }
        }
#pragma unroll
        for (int l = 0; l < 4; l++) {
            float2 r0 = relu2(acc[l][0]), r1 = relu2(acc[l][1]);
            st4(A + 1600 + rgt * 272 + l * 64 + jg4, make_float4(r0.x, r0.y, r1.x, r1.y));
        }
    }
    __syncwarp();

    // ---- Stage 3: QKV -> qkv[t][l][192] ----
#pragma unroll
    for (int m = 0; m < 3; m++) {
        ulonglong2 bm = ld128(attn_in_b + 64 * m + jg4);
        u64 acc[4][2];
#pragma unroll
        for (int l = 0; l < 4; l++) { acc[l][0] = bm.x; acc[l][1] = bm.y; }
#pragma unroll 2
        for (int k = 0; k < 64; k += 4) {
            float ev[4][4];
#pragma unroll
            for (int l = 0; l < 4; l++) {
                float4 v = ld4(A + 1600 + rgt * 272 + l * 64 + k);
                ev[l][0] = v.x; ev[l][1] = v.y; ev[l][2] = v.z; ev[l][3] = v.w;
            }
#pragma unroll
            for (int kk = 0; kk < 4; kk++) {
                ulonglong2 w = ld128(attn_in_w + (k + kk) * 192 + 64 * m + jg4);
#pragma unroll
                for (int l = 0; l < 4; l++) {
                    u64 d = dup2(ev[l][kk]);
                    acc[l][0] = ffma2(d, w.x, acc[l][0]);
                    acc[l][1] = ffma2(d, w.y, acc[l][1]);
                }
            }
        }
#pragma unroll
        for (int l = 0; l < 4; l++) {
            float a0, a1, a2, a3; upk2(acc[l][0], a0, a1); upk2(acc[l][1], a2, a3);
            st4(A + rgt * 784 + l * 192 + m * 64 + jg4, make_float4(a0, a1, a2, a3));
        }
    }
    __syncwarp();

    // ---- Stage 4: attention, 32 lanes = 2 TLs x (4 heads x 4 queries) ----
    {
        const int t4 = rgt, r4 = lane & 15, hh = r4 >> 2, ql = r4 & 3;
        const float* qb = A + t4 * 784 + ql * 192 + hh * 16;
        float q[16];
#pragma unroll
        for (int i = 0; i < 4; i++) {
            float4 v = ld4(qb + 4 * i);
            q[4*i] = v.x; q[4*i+1] = v.y; q[4*i+2] = v.z; q[4*i+3] = v.w;
        }
        float sc[4];
#pragma unroll
        for (int kl = 0; kl < 4; kl++) {
            const float* kb = A + t4 * 784 + kl * 192 + 64 + hh * 16;
            float d = 0.f;
#pragma unroll
            for (int i = 0; i < 4; i++) {
                float4 v = ld4(kb + 4 * i);
                d = fmaf(q[4*i], v.x, d); d = fmaf(q[4*i+1], v.y, d);
                d = fmaf(q[4*i+2], v.z, d); d = fmaf(q[4*i+3], v.w, d);
            }
            sc[kl] = d * 0.25f;
        }
        float mx = fmaxf(fmaxf(sc[0], sc[1]), fmaxf(sc[2], sc[3]));
        float es = 0.f;
#pragma unroll
        for (int kl = 0; kl < 4; kl++) { sc[kl] = __expf(sc[kl] - mx); es += sc[kl]; }
        float inv = 1.f / es;
#pragma unroll
        for (int kl = 0; kl < 4; kl++) sc[kl] *= inv;
        float o[16];
#pragma unroll
        for (int i = 0; i < 4; i++) {
            float ox = 0.f, oy = 0.f, oz = 0.f, ow = 0.f;
#pragma unroll
            for (int kl = 0; kl < 4; kl++) {
                float4 v = ld4(A + t4 * 784 + kl * 192 + 128 + hh * 16 + 4 * i);
                ox = fmaf(sc[kl], v.x, ox); oy = fmaf(sc[kl], v.y, oy);
                oz = fmaf(sc[kl], v.z, oz); ow = fmaf(sc[kl], v.w, ow);
            }
            o[4*i] = ox; o[4*i+1] = oy; o[4*i+2] = oz; o[4*i+3] = ow;
        }
        __syncwarp();
#pragma unroll
        for (int i = 0; i < 4; i++)
            st4(A + t4 * 272 + ql * 64 + hh * 16 + 4 * i,
                make_float4(o[4*i], o[4*i+1], o[4*i+2], o[4*i+3]));
    }
    __syncwarp();

    // ---- Stage 5a: obar[t][64] = mean over lanes ----
#pragma unroll
    for (int ii = 0; ii < 4; ii++) {
        int i = lane + 32 * ii;
        int t = i >> 6, jj = i & 63;
        float s = A[t*272 + jj] + A[t*272 + 64 + jj] + A[t*272 + 128 + jj] + A[t*272 + 192 + jj];
        A[1088 + t * 80 + jj] = 0.25f * s;
    }
    __syncwarp();

    // ---- Stage 5b: ctx = obar @ Wout + b -> featp[0:64][row] ----
    {
        ulonglong2 ob = ld128(attn_out_b + jg4);
        u64 a0 = ob.x, a1 = ob.y;
#pragma unroll 2
        for (int k = 0; k < 64; k += 4) {
            float4 v = ld4(A + 1088 + rgt * 80 + k);
            float ov[4] = {v.x, v.y, v.z, v.w};
#pragma unroll
            for (int kk = 0; kk < 4; kk++) {
                ulonglong2 w = ld128(attn_out_w + (k + kk) * 64 + jg4);
                u64 d = dup2(ov[kk]);
                a0 = ffma2(d, w.x, a0);
                a1 = ffma2(d, w.y, a1);
            }
        }
        const int row = warp * 2 + rgt;
        float c0, c1, c2, c3; upk2(a0, c0, c1); upk2(a1, c2, c3);
        featp[jg4 + 0][row] = c0; featp[jg4 + 1][row] = c1;
        featp[jg4 + 2][row] = c2; featp[jg4 + 3][row] = c3;
    }

    // ---- Stage 6: phase MLP (warp handles 2 TLs, weights reused) ----
    {
        ulonglong2 PB = ld128(phase_b1 + j4);
        ulonglong2 PW[5];
#pragma unroll
        for (int k = 0; k < 5; k++) PW[k] = ld128(phase_w1 + k * 128 + j4);
#pragma unroll
        for (int t = 0; t < 2; t++) {
            const int n = t ? nb : na;
            float4 po = ld4(phase_onehot + 4 * n);
            float x[5] = {po.x, po.y, po.z, po.w, ee[t]};
            u64 lo = PB.x, hi = PB.y;
#pragma unroll
            for (int k = 0; k < 5; k++) {
                u64 d = dup2(x[k]);
                lo = ffma2(d, PW[k].x, lo);
                hi = ffma2(d, PW[k].y, hi);
            }
            float2 r0 = relu2(lo), r1 = relu2(hi);
            st4(A + 1280 + t * 144 + j4, make_float4(r0.x, r0.y, r1.x, r1.y));
        }
        __syncwarp();

        ulonglong2 pb2 = ld128(phase_b2 + j4);
        u64 acc[2][2];
        acc[0][0] = acc[1][0] = pb2.x;
        acc[0][1] = acc[1][1] = pb2.y;
#pragma unroll 2
        for (int k = 0; k < 128; k += 4) {
            float4 p0 = ld4(A + 1280 + k);
            float4 p1 = ld4(A + 1280 + 144 + k);
            float ph2[2][4] = {{p0.x, p0.y, p0.z, p0.w}, {p1.x, p1.y, p1.z, p1.w}};
#pragma unroll
            for (int kk = 0; kk < 4; kk++) {
                ulonglong2 w = ld128(phase_w2 + (k + kk) * 128 + j4);
#pragma unroll
                for (int t = 0; t < 2; t++) {
                    u64 d = dup2(ph2[t][kk]);
                    acc[t][0] = ffma2(d, w.x, acc[t][0]);
                    acc[t][1] = ffma2(d, w.y, acc[t][1]);
                }
            }
        }
#pragma unroll
        for (int t = 0; t < 2; t++) {
            const int row = warp * 2 + t;
            float2 r0 = relu2(acc[t][0]), r1 = relu2(acc[t][1]);
            featp[64 + j4 + 0][row] = r0.x; featp[64 + j4 + 1][row] = r0.y;
            featp[64 + j4 + 2][row] = r1.x; featp[64 + j4 + 3][row] = r1.y;
        }
    }

    // ---- Stage 7: region embedding -> featp[192:200][row] ----
    if (lane < 16) {
        const int t = lane >> 3, f = lane & 7;
        const int n = t ? nb : na;
        int rid = region_ids[n];
        rid = min(max(rid, 0), 3);
        featp[192 + f][warp * 2 + t] = region_table[rid * 8 + f];
    }
    __syncthreads();

    // ---- Stage 8: head GEMM, block-cooperative over 8 rows; thread owns j=tid ----
    {
        const int j = tid;   // 0..127
        u64 acc8[4];
        u64 bj = dup2(head_b1[j]);
#pragma unroll
        for (int r = 0; r < 4; r++) acc8[r] = bj;
#pragma unroll 8
        for (int k = 0; k < 200; k++) {
            u64 wk = dup2(head_w1[k * 128 + j]);
            ulonglong2 fa = ld128(&featp[k][0]);   // rows 0-3
            ulonglong2 fb = ld128(&featp[k][4]);   // rows 4-7
            acc8[0] = ffma2(fa.x, wk, acc8[0]);
            acc8[1] = ffma2(fa.y, wk, acc8[1]);
            acc8[2] = ffma2(fb.x, wk, acc8[2]);
            acc8[3] = ffma2(fb.y, wk, acc8[3]);
        }
        const float w2j = head_w2[j];
        u64 s[4];
#pragma unroll
        for (int r = 0; r < 4; r++) {
            float2 a = relu2(acc8[r]);
            s[r] = pk2(a.x * w2j, a.y * w2j);
        }
#pragma unroll
        for (int off = 16; off > 0; off >>= 1) {
#pragma unroll
            for (int r = 0; r < 4; r++)
                s[r] = add2(s[r], __shfl_xor_sync(0xffffffffu, s[r], off));
        }
        if (lane == 0) {
#pragma unroll
            for (int r = 0; r < 4; r++) {
                float a, b; upk2(s[r], a, b);
                partial[warp][2 * r] = a; partial[warp][2 * r + 1] = b;
            }
        }
    }
    __syncthreads();

    if (warp == 0 && lane < 8) {
        const int row = lane;
        const int n = blockIdx.x * TLB + row;
        if (n < N) {
            float mean = partial[0][row] + partial[1][row] + partial[2][row] + partial[3][row]
                       + head_b2[0];
            float ls = log_std[0];
            float sd = expf(ls);
            float nz = noise[n];
            float act = mean + sd * nz;
            out[n] = fminf(fmaxf(act, -1.0f), 1.0f);
            out[N + n] = -0.5f * (nz * nz + 2.0f * ls + 1.8378770664093454f);
        }
    }
}

extern "C" void kernel_launch(void* const* d_in, const int* in_sizes, int n_in,
                              void* d_out, int out_size)
{
    const float* queue        = (const float*)d_in[0];
    const float* waiting      = (const float*)d_in[1];
    const float* phase_onehot = (const float*)d_in[2];
    const float* elapsed      = (const float*)d_in[3];
    const int*   region_ids   = (const int*)  d_in[4];
    const float* noise        = (const float*)d_in[5];
    const float* lane_w1      = (const float*)d_in[6];
    const float* lane_b1      = (const float*)d_in[7];
    const float* lane_w2      = (const float*)d_in[8];
    const float* lane_b2      = (const float*)d_in[9];
    const float* attn_in_w    = (const float*)d_in[10];
    const float* attn_in_b    = (const float*)d_in[11];
    const float* attn_out_w   = (const float*)d_in[12];
    const float* attn_out_b   = (const float*)d_in[13];
    const float* phase_w1     = (const float*)d_in[14];
    const float* phase_b1     = (const float*)d_in[15];
    const float* phase_w2     = (const float*)d_in[16];
    const float* phase_b2     = (const float*)d_in[17];
    const float* region_table = (const float*)d_in[18];
    const float* head_w1      = (const float*)d_in[19];
    const float* head_b1      = (const float*)d_in[20];
    const float* head_w2      = (const float*)d_in[21];
    const float* head_b2      = (const float*)d_in[22];
    const float* log_std      = (const float*)d_in[23];

    const int N = in_sizes[3];
    float* out = (float*)d_out;

    int blocks = (N + TLB - 1) / TLB;
    policy_kernel<<<blocks, NWARP * 32>>>(
        queue, waiting, phase_onehot, elapsed, region_ids, noise,
        lane_w1, lane_b1, lane_w2, lane_b2,
        attn_in_w, attn_in_b, attn_out_w, attn_out_b,
        phase_w1, phase_b1, phase_w2, phase_b2,
        region_table, head_w1, head_b1, head_w2, head_b2, log_std,
        out, N);
}

// round 6
// speedup vs baseline: 1.0693x; 1.0693x over previous
#include <cuda_runtime.h>
#include <math.h>

typedef unsigned long long u64;
typedef unsigned int u32;

#define NWARP 4
#define TLB   8
#define BUF   2208

__device__ __forceinline__ u64 pk2(float a, float b) {
    u64 r; asm("mov.b64 %0, {%1, %2};" : "=l"(r) : "r"(__float_as_uint(a)), "r"(__float_as_uint(b)));
    return r;
}
__device__ __forceinline__ void upk2(u64 v, float& a, float& b) {
    u32 x, y; asm("mov.b64 {%0, %1}, %2;" : "=r"(x), "=r"(y) : "l"(v));
    a = __uint_as_float(x); b = __uint_as_float(y);
}
__device__ __forceinline__ u64 dup2(float a) { return pk2(a, a); }
__device__ __forceinline__ u64 ffma2(u64 a, u64 b, u64 c) {
    u64 d; asm("fma.rn.f32x2 %0, %1, %2, %3;" : "=l"(d) : "l"(a), "l"(b), "l"(c)); return d;
}
__device__ __forceinline__ u64 add2(u64 a, u64 b) {
    u64 d; asm("add.rn.f32x2 %0, %1, %2;" : "=l"(d) : "l"(a), "l"(b)); return d;
}
__device__ __forceinline__ float2 relu2(u64 v) {
    float a, b; upk2(v, a, b); return make_float2(fmaxf(a, 0.f), fmaxf(b, 0.f));
}
__device__ __forceinline__ ulonglong2 ld128(const float* p) { return *reinterpret_cast<const ulonglong2*>(p); }
__device__ __forceinline__ float4 ld4(const float* p)       { return *reinterpret_cast<const float4*>(p); }
__device__ __forceinline__ void st4(float* p, float4 v)     { *reinterpret_cast<float4*>(p) = v; }
__device__ __forceinline__ float relu(float x) { return fmaxf(x, 0.f); }

// per-warp scratch regions (floats):
//   h    : t*528 + l*128 + j          [0,1056)
//   qkv  : t*816 + l*200 + m*64 + j   [0,1632)   (h dead)
//   o    : t*280 + l*68 + j           [0,548)
//   obar : 1088 + t*80 + j
//   emb  : 1664 + t*272 + l*64 + j
// block-shared aliases (after stage 5):
//   phS  : wb[0][row*132 + k]   rows 0..7, k 0..127
//   Pp0/1: wb[1]/wb[2] [row*128 + j]

__global__ __launch_bounds__(NWARP * 32)
void policy_kernel(
    const float* __restrict__ queue, const float* __restrict__ waiting,
    const float* __restrict__ phase_onehot, const float* __restrict__ elapsed,
    const int*   __restrict__ region_ids, const float* __restrict__ noise,
    const float* __restrict__ lane_w1, const float* __restrict__ lane_b1,
    const float* __restrict__ lane_w2, const float* __restrict__ lane_b2,
    const float* __restrict__ attn_in_w, const float* __restrict__ attn_in_b,
    const float* __restrict__ attn_out_w, const float* __restrict__ attn_out_b,
    const float* __restrict__ phase_w1, const float* __restrict__ phase_b1,
    const float* __restrict__ phase_w2, const float* __restrict__ phase_b2,
    const float* __restrict__ region_table,
    const float* __restrict__ head_w1, const float* __restrict__ head_b1,
    const float* __restrict__ head_w2, const float* __restrict__ head_b2,
    const float* __restrict__ log_std,
    float* __restrict__ out, int N)
{
    __shared__ float wb[NWARP][BUF];
    __shared__ float featp[200][12];
    __shared__ float partial[NWARP][8];

    const int tid  = threadIdx.x;
    const int warp = tid >> 5, lane = tid & 31;
    const int n0   = blockIdx.x * TLB + warp * 2;
    float* A = wb[warp];
    float* phS = &wb[0][0];
    float* Pp0 = &wb[1][0];
    float* Pp1 = &wb[2][0];

    const int rgt = lane >> 4;
    const int jg4 = (lane & 15) * 4;
    const int j4  = lane * 4;

    const int na = min(n0,     N - 1);
    const int nb = min(n0 + 1, N - 1);
    const float ee[2] = { elapsed[na], elapsed[nb] };

    // ---- S1: lane MLP L1 -> h ----
    {
        ulonglong2 W0 = ld128(lane_w1 + j4);
        ulonglong2 W1 = ld128(lane_w1 + 128 + j4);
        ulonglong2 W2 = ld128(lane_w1 + 256 + j4);
        ulonglong2 BB = ld128(lane_b1 + j4);
#pragma unroll
        for (int t = 0; t < 2; t++) {
            const int n = t ? nb : na;
            float4 qv = ld4(queue + 4 * n);
            float4 wv = ld4(waiting + 4 * n);
            u64 ed = dup2(ee[t]);
            float qa[4] = {qv.x, qv.y, qv.z, qv.w};
            float wa[4] = {wv.x, wv.y, wv.z, wv.w};
#pragma unroll
            for (int l = 0; l < 4; l++) {
                u64 qd = dup2(qa[l]), wd = dup2(wa[l]);
                u64 lo = ffma2(qd, W0.x, BB.x); lo = ffma2(wd, W1.x, lo); lo = ffma2(ed, W2.x, lo);
                u64 hi = ffma2(qd, W0.y, BB.y); hi = ffma2(wd, W1.y, hi); hi = ffma2(ed, W2.y, hi);
                float2 r0 = relu2(lo), r1 = relu2(hi);
                st4(A + t * 528 + l * 128 + j4, make_float4(r0.x, r0.y, r1.x, r1.y));
            }
        }
    }
    __syncwarp();

    // ---- S2: lane MLP L2 -> emb ----
    {
        ulonglong2 bb = ld128(lane_b2 + jg4);
        u64 acc[4][2];
#pragma unroll
        for (int l = 0; l < 4; l++) { acc[l][0] = bb.x; acc[l][1] = bb.y; }
#pragma unroll 2
        for (int k = 0; k < 128; k += 4) {
            float hv[4][4];
#pragma unroll
            for (int l = 0; l < 4; l++) {
                float4 v = ld4(A + rgt * 528 + l * 128 + k);
                hv[l][0] = v.x; hv[l][1] = v.y; hv[l][2] = v.z; hv[l][3] = v.w;
            }
#pragma unroll
            for (int kk = 0; kk < 4; kk++) {
                ulonglong2 w = ld128(lane_w2 + (k + kk) * 64 + jg4);
#pragma unroll
                for (int l = 0; l < 4; l++) {
                    u64 d = dup2(hv[l][kk]);
                    acc[l][0] = ffma2(d, w.x, acc[l][0]);
                    acc[l][1] = ffma2(d, w.y, acc[l][1]);
                }
            }
        }
#pragma unroll
        for (int l = 0; l < 4; l++) {
            float2 r0 = relu2(acc[l][0]), r1 = relu2(acc[l][1]);
            st4(A + 1664 + rgt * 272 + l * 64 + jg4, make_float4(r0.x, r0.y, r1.x, r1.y));
        }
    }
    __syncwarp();

    // ---- S3: QKV ----
#pragma unroll
    for (int m = 0; m < 3; m++) {
        ulonglong2 bm = ld128(attn_in_b + 64 * m + jg4);
        u64 acc[4][2];
#pragma unroll
        for (int l = 0; l < 4; l++) { acc[l][0] = bm.x; acc[l][1] = bm.y; }
#pragma unroll 2
        for (int k = 0; k < 64; k += 4) {
            float ev[4][4];
#pragma unroll
            for (int l = 0; l < 4; l++) {
                float4 v = ld4(A + 1664 + rgt * 272 + l * 64 + k);
                ev[l][0] = v.x; ev[l][1] = v.y; ev[l][2] = v.z; ev[l][3] = v.w;
            }
#pragma unroll
            for (int kk = 0; kk < 4; kk++) {
                ulonglong2 w = ld128(attn_in_w + (k + kk) * 192 + 64 * m + jg4);
#pragma unroll
                for (int l = 0; l < 4; l++) {
                    u64 d = dup2(ev[l][kk]);
                    acc[l][0] = ffma2(d, w.x, acc[l][0]);
                    acc[l][1] = ffma2(d, w.y, acc[l][1]);
                }
            }
        }
#pragma unroll
        for (int l = 0; l < 4; l++) {
            float a0, a1, a2, a3; upk2(acc[l][0], a0, a1); upk2(acc[l][1], a2, a3);
            st4(A + rgt * 816 + l * 200 + m * 64 + jg4, make_float4(a0, a1, a2, a3));
        }
    }
    __syncwarp();

    // ---- S4: attention ----
    {
        const int t4 = rgt, r4 = lane & 15, hh = r4 >> 2, ql = r4 & 3;
        const float* qb = A + t4 * 816 + ql * 200 + hh * 16;
        float q[16];
#pragma unroll
        for (int i = 0; i < 4; i++) {
            float4 v = ld4(qb + 4 * i);
            q[4*i] = v.x; q[4*i+1] = v.y; q[4*i+2] = v.z; q[4*i+3] = v.w;
        }
        float sc[4];
#pragma unroll
        for (int kl = 0; kl < 4; kl++) {
            const float* kb = A + t4 * 816 + kl * 200 + 64 + hh * 16;
            float d = 0.f;
#pragma unroll
            for (int i = 0; i < 4; i++) {
                float4 v = ld4(kb + 4 * i);
                d = fmaf(q[4*i], v.x, d); d = fmaf(q[4*i+1], v.y, d);
                d = fmaf(q[4*i+2], v.z, d); d = fmaf(q[4*i+3], v.w, d);
            }
            sc[kl] = d * 0.25f;
        }
        float mx = fmaxf(fmaxf(sc[0], sc[1]), fmaxf(sc[2], sc[3]));
        float es = 0.f;
#pragma unroll
        for (int kl = 0; kl < 4; kl++) { sc[kl] = __expf(sc[kl] - mx); es += sc[kl]; }
        float inv = 1.f / es;
#pragma unroll
        for (int kl = 0; kl < 4; kl++) sc[kl] *= inv;
        float o[16];
#pragma unroll
        for (int i = 0; i < 4; i++) {
            float ox = 0.f, oy = 0.f, oz = 0.f, ow = 0.f;
#pragma unroll
            for (int kl = 0; kl < 4; kl++) {
                float4 v = ld4(A + t4 * 816 + kl * 200 + 128 + hh * 16 + 4 * i);
                ox = fmaf(sc[kl], v.x, ox); oy = fmaf(sc[kl], v.y, oy);
                oz = fmaf(sc[kl], v.z, oz); ow = fmaf(sc[kl], v.w, ow);
            }
            o[4*i] = ox; o[4*i+1] = oy; o[4*i+2] = oz; o[4*i+3] = ow;
        }
        __syncwarp();
#pragma unroll
        for (int i = 0; i < 4; i++)
            st4(A + t4 * 280 + ql * 68 + hh * 16 + 4 * i,
                make_float4(o[4*i], o[4*i+1], o[4*i+2], o[4*i+3]));
    }
    __syncwarp();

    // ---- S5a: obar ----
#pragma unroll
    for (int ii = 0; ii < 4; ii++) {
        int i = lane + 32 * ii;
        int t = i >> 6, jj = i & 63;
        float s = A[t*280 + jj] + A[t*280 + 68 + jj] + A[t*280 + 136 + jj] + A[t*280 + 204 + jj];
        A[1088 + t * 80 + jj] = 0.25f * s;
    }
    __syncthreads();   // o reads done block-wide before phS overwrites wb[0]

    // ---- S5b: ctx -> featp[0:64) ----
    {
        ulonglong2 ob = ld128(attn_out_b + jg4);
        u64 a0 = ob.x, a1 = ob.y;
#pragma unroll 2
        for (int k = 0; k < 64; k += 4) {
            float4 v = ld4(A + 1088 + rgt * 80 + k);
            float ov[4] = {v.x, v.y, v.z, v.w};
#pragma unroll
            for (int kk = 0; kk < 4; kk++) {
                ulonglong2 w = ld128(attn_out_w + (k + kk) * 64 + jg4);
                u64 d = dup2(ov[kk]);
                a0 = ffma2(d, w.x, a0);
                a1 = ffma2(d, w.y, a1);
            }
        }
        const int row = warp * 2 + rgt;
        float c0, c1, c2, c3; upk2(a0, c0, c1); upk2(a1, c2, c3);
        featp[jg4 + 0][row] = c0; featp[jg4 + 1][row] = c1;
        featp[jg4 + 2][row] = c2; featp[jg4 + 3][row] = c3;
    }

    // ---- S6 L1: phase hidden -> phS[row][k] (block-shared) ----
    {
        ulonglong2 PB = ld128(phase_b1 + j4);
        ulonglong2 PW[5];
#pragma unroll
        for (int k = 0; k < 5; k++) PW[k] = ld128(phase_w1 + k * 128 + j4);
#pragma unroll
        for (int t = 0; t < 2; t++) {
            const int n = t ? nb : na;
            float4 po = ld4(phase_onehot + 4 * n);
            float x[5] = {po.x, po.y, po.z, po.w, ee[t]};
            u64 lo = PB.x, hi = PB.y;
#pragma unroll
            for (int k = 0; k < 5; k++) {
                u64 d = dup2(x[k]);
                lo = ffma2(d, PW[k].x, lo);
                hi = ffma2(d, PW[k].y, hi);
            }
            float2 r0 = relu2(lo), r1 = relu2(hi);
            st4(phS + (2 * warp + t) * 132 + j4, make_float4(r0.x, r0.y, r1.x, r1.y));
        }
    }
    __syncthreads();   // phS complete

    // ---- S6 L2 partial: quadrant coop (k-half x row-half), out Pp[kh][row][j] ----
    {
        const int kh = warp & 1, rh = warp >> 1;
        const int k0 = 64 * kh, r0 = 4 * rh;
        float* Pp = kh ? Pp1 : Pp0;
        u64 acc[4][2];
#pragma unroll
        for (int r = 0; r < 4; r++) acc[r][0] = acc[r][1] = 0ULL;
        for (int k = k0; k < k0 + 64; k += 4) {
            float av[4][4];
#pragma unroll
            for (int r = 0; r < 4; r++) {
                float4 v = ld4(phS + (r0 + r) * 132 + k);
                av[r][0] = v.x; av[r][1] = v.y; av[r][2] = v.z; av[r][3] = v.w;
            }
#pragma unroll
            for (int kk = 0; kk < 4; kk++) {
                ulonglong2 w = ld128(phase_w2 + (k + kk) * 128 + j4);
#pragma unroll
                for (int r = 0; r < 4; r++) {
                    u64 d = dup2(av[r][kk]);
                    acc[r][0] = ffma2(d, w.x, acc[r][0]);
                    acc[r][1] = ffma2(d, w.y, acc[r][1]);
                }
            }
        }
#pragma unroll
        for (int r = 0; r < 4; r++) {
            float a0, a1, a2, a3; upk2(acc[r][0], a0, a1); upk2(acc[r][1], a2, a3);
            st4(Pp + (r0 + r) * 128 + j4, make_float4(a0, a1, a2, a3));
        }
    }
    __syncthreads();

    // ---- S6 L2 final: reduce halves + bias + relu -> featp[64:192) ; S7 region ----
    {
        float4 b = ld4(phase_b2 + j4);
#pragma unroll
        for (int rr = 0; rr < 2; rr++) {
            const int r = 2 * warp + rr;
            float4 p0 = ld4(Pp0 + r * 128 + j4);
            float4 p1 = ld4(Pp1 + r * 128 + j4);
            featp[64 + j4 + 0][r] = relu(p0.x + p1.x + b.x);
            featp[64 + j4 + 1][r] = relu(p0.y + p1.y + b.y);
            featp[64 + j4 + 2][r] = relu(p0.z + p1.z + b.z);
            featp[64 + j4 + 3][r] = relu(p0.w + p1.w + b.w);
        }
    }
    if (lane < 16) {
        const int t = lane >> 3, f = lane & 7;
        const int n = t ? nb : na;
        int rid = region_ids[n];
        rid = min(max(rid, 0), 3);
        featp[192 + f][warp * 2 + t] = region_table[rid * 8 + f];
    }
    __syncthreads();

    // ---- S8: head GEMM, thread owns j=tid, rows packed in f32x2 ----
    {
        const int j = tid;
        u64 acc8[4];
        u64 bj = dup2(head_b1[j]);
#pragma unroll
        for (int r = 0; r < 4; r++) acc8[r] = bj;
#pragma unroll 8
        for (int k = 0; k < 200; k++) {
            u64 wk = dup2(head_w1[k * 128 + j]);
            ulonglong2 fa = ld128(&featp[k][0]);
            ulonglong2 fb = ld128(&featp[k][4]);
            acc8[0] = ffma2(fa.x, wk, acc8[0]);
            acc8[1] = ffma2(fa.y, wk, acc8[1]);
            acc8[2] = ffma2(fb.x, wk, acc8[2]);
            acc8[3] = ffma2(fb.y, wk, acc8[3]);
        }
        const float w2j = head_w2[j];
        u64 s[4];
#pragma unroll
        for (int r = 0; r < 4; r++) {
            float2 a = relu2(acc8[r]);
            s[r] = pk2(a.x * w2j, a.y * w2j);
        }
#pragma unroll
        for (int off = 16; off > 0; off >>= 1) {
#pragma unroll
            for (int r = 0; r < 4; r++)
                s[r] = add2(s[r], __shfl_xor_sync(0xffffffffu, s[r], off));
        }
        if (lane == 0) {
#pragma unroll
            for (int r = 0; r < 4; r++) {
                float a, b; upk2(s[r], a, b);
                partial[warp][2 * r] = a; partial[warp][2 * r + 1] = b;
            }
        }
    }
    __syncthreads();

    if (warp == 0 && lane < 8) {
        const int row = lane;
        const int n = blockIdx.x * TLB + row;
        if (n < N) {
            float mean = partial[0][row] + partial[1][row] + partial[2][row] + partial[3][row]
                       + head_b2[0];
            float ls = log_std[0];
            float sd = expf(ls);
            float nz = noise[n];
            float act = mean + sd * nz;
            out[n] = fminf(fmaxf(act, -1.0f), 1.0f);
            out[N + n] = -0.5f * (nz * nz + 2.0f * ls + 1.8378770664093454f);
        }
    }
}

extern "C" void kernel_launch(void* const* d_in, const int* in_sizes, int n_in,
                              void* d_out, int out_size)
{
    const float* queue        = (const float*)d_in[0];
    const float* waiting      = (const float*)d_in[1];
    const float* phase_onehot = (const float*)d_in[2];
    const float* elapsed      = (const float*)d_in[3];
    const int*   region_ids   = (const int*)  d_in[4];
    const float* noise        = (const float*)d_in[5];
    const float* lane_w1      = (const float*)d_in[6];
    const float* lane_b1      = (const float*)d_in[7];
    const float* lane_w2      = (const float*)d_in[8];
    const float* lane_b2      = (const float*)d_in[9];
    const float* attn_in_w    = (const float*)d_in[10];
    const float* attn_in_b    = (const float*)d_in[11];
    const float* attn_out_w   = (const float*)d_in[12];
    const float* attn_out_b   = (const float*)d_in[13];
    const float* phase_w1     = (const float*)d_in[14];
    const float* phase_b1     = (const float*)d_in[15];
    const float* phase_w2     = (const float*)d_in[16];
    const float* phase_b2     = (const float*)d_in[17];
    const float* region_table = (const float*)d_in[18];
    const float* head_w1      = (const float*)d_in[19];
    const float* head_b1      = (const float*)d_in[20];
    const float* head_w2      = (const float*)d_in[21];
    const float* head_b2      = (const float*)d_in[22];
    const float* log_std      = (const float*)d_in[23];

    const int N = in_sizes[3];
    float* out = (float*)d_out;

    int blocks = (N + TLB - 1) / TLB;
    policy_kernel<<<blocks, NWARP * 32>>>(
        queue, waiting, phase_onehot, elapsed, region_ids, noise,
        lane_w1, lane_b1, lane_w2, lane_b2,
        attn_in_w, attn_in_b, attn_out_w, attn_out_b,
        phase_w1, phase_b1, phase_w2, phase_b2,
        region_table, head_w1, head_b1, head_w2, head_b2, log_std,
        out, N);
}

// round 9
// speedup vs baseline: 1.0700x; 1.0007x over previous
#include <cuda_runtime.h>
#include <math.h>

typedef unsigned long long u64;
typedef unsigned int u32;

#define NWARP 4
#define TLB   8
#define BUF   2208

__device__ __forceinline__ u64 pk2(float a, float b) {
    u64 r; asm("mov.b64 %0, {%1, %2};" : "=l"(r) : "r"(__float_as_uint(a)), "r"(__float_as_uint(b)));
    return r;
}
__device__ __forceinline__ void upk2(u64 v, float& a, float& b) {
    u32 x, y; asm("mov.b64 {%0, %1}, %2;" : "=r"(x), "=r"(y) : "l"(v));
    a = __uint_as_float(x); b = __uint_as_float(y);
}
__device__ __forceinline__ u64 dup2(float a) { return pk2(a, a); }
__device__ __forceinline__ u64 ffma2(u64 a, u64 b, u64 c) {
    u64 d; asm("fma.rn.f32x2 %0, %1, %2, %3;" : "=l"(d) : "l"(a), "l"(b), "l"(c)); return d;
}
__device__ __forceinline__ u64 add2(u64 a, u64 b) {
    u64 d; asm("add.rn.f32x2 %0, %1, %2;" : "=l"(d) : "l"(a), "l"(b)); return d;
}
__device__ __forceinline__ float2 relu2(u64 v) {
    float a, b; upk2(v, a, b); return make_float2(fmaxf(a, 0.f), fmaxf(b, 0.f));
}
__device__ __forceinline__ ulonglong2 ld128(const float* p) { return *reinterpret_cast<const ulonglong2*>(p); }
__device__ __forceinline__ float4 ld4(const float* p)       { return *reinterpret_cast<const float4*>(p); }
__device__ __forceinline__ void st4(float* p, float4 v)     { *reinterpret_cast<float4*>(p) = v; }
__device__ __forceinline__ float relu(float x) { return fmaxf(x, 0.f); }

// per-warp scratch regions (floats):
//   h    : t*528 + l*128 + j          [0,1056)
//   qkv  : t*816 + l*200 + m*64 + j   [0,1632)   (h dead)
//   o    : t*280 + l*68 + j           [0,548)
//   obar : 1088 + t*80 + j
//   emb  : 1664 + t*272 + l*64 + j
// block-shared aliases (after stage 5):
//   phS  : wb[0][row*132 + k]   rows 0..7, k 0..127
//   Pp0/1: wb[1]/wb[2] [row*128 + j]

__global__ __launch_bounds__(NWARP * 32)
void policy_kernel(
    const float* __restrict__ queue, const float* __restrict__ waiting,
    const float* __restrict__ phase_onehot, const float* __restrict__ elapsed,
    const int*   __restrict__ region_ids, const float* __restrict__ noise,
    const float* __restrict__ lane_w1, const float* __restrict__ lane_b1,
    const float* __restrict__ lane_w2, const float* __restrict__ lane_b2,
    const float* __restrict__ attn_in_w, const float* __restrict__ attn_in_b,
    const float* __restrict__ attn_out_w, const float* __restrict__ attn_out_b,
    const float* __restrict__ phase_w1, const float* __restrict__ phase_b1,
    const float* __restrict__ phase_w2, const float* __restrict__ phase_b2,
    const float* __restrict__ region_table,
    const float* __restrict__ head_w1, const float* __restrict__ head_b1,
    const float* __restrict__ head_w2, const float* __restrict__ head_b2,
    const float* __restrict__ log_std,
    float* __restrict__ out, int N)
{
    __shared__ float wb[NWARP][BUF];
    __shared__ float featp[200][12];
    __shared__ float partial[NWARP][8];

    const int tid  = threadIdx.x;
    const int warp = tid >> 5, lane = tid & 31;
    const int n0   = blockIdx.x * TLB + warp * 2;
    float* A = wb[warp];
    float* phS = &wb[0][0];
    float* Pp0 = &wb[1][0];
    float* Pp1 = &wb[2][0];

    const int rgt = lane >> 4;
    const int jg4 = (lane & 15) * 4;
    const int j4  = lane * 4;

    const int na = min(n0,     N - 1);
    const int nb = min(n0 + 1, N - 1);
    const float ee[2] = { elapsed[na], elapsed[nb] };

    // ---- S1: lane MLP L1 -> h ----
    {
        ulonglong2 W0 = ld128(lane_w1 + j4);
        ulonglong2 W1 = ld128(lane_w1 + 128 + j4);
        ulonglong2 W2 = ld128(lane_w1 + 256 + j4);
        ulonglong2 BB = ld128(lane_b1 + j4);
#pragma unroll
        for (int t = 0; t < 2; t++) {
            const int n = t ? nb : na;
            float4 qv = ld4(queue + 4 * n);
            float4 wv = ld4(waiting + 4 * n);
            u64 ed = dup2(ee[t]);
            float qa[4] = {qv.x, qv.y, qv.z, qv.w};
            float wa[4] = {wv.x, wv.y, wv.z, wv.w};
#pragma unroll
            for (int l = 0; l < 4; l++) {
                u64 qd = dup2(qa[l]), wd = dup2(wa[l]);
                u64 lo = ffma2(qd, W0.x, BB.x); lo = ffma2(wd, W1.x, lo); lo = ffma2(ed, W2.x, lo);
                u64 hi = ffma2(qd, W0.y, BB.y); hi = ffma2(wd, W1.y, hi); hi = ffma2(ed, W2.y, hi);
                float2 r0 = relu2(lo), r1 = relu2(hi);
                st4(A + t * 528 + l * 128 + j4, make_float4(r0.x, r0.y, r1.x, r1.y));
            }
        }
    }
    __syncwarp();

    // ---- S2: lane MLP L2 -> emb ----
    {
        ulonglong2 bb = ld128(lane_b2 + jg4);
        u64 acc[4][2];
#pragma unroll
        for (int l = 0; l < 4; l++) { acc[l][0] = bb.x; acc[l][1] = bb.y; }
#pragma unroll 2
        for (int k = 0; k < 128; k += 4) {
            float hv[4][4];
#pragma unroll
            for (int l = 0; l < 4; l++) {
                float4 v = ld4(A + rgt * 528 + l * 128 + k);
                hv[l][0] = v.x; hv[l][1] = v.y; hv[l][2] = v.z; hv[l][3] = v.w;
            }
#pragma unroll
            for (int kk = 0; kk < 4; kk++) {
                ulonglong2 w = ld128(lane_w2 + (k + kk) * 64 + jg4);
#pragma unroll
                for (int l = 0; l < 4; l++) {
                    u64 d = dup2(hv[l][kk]);
                    acc[l][0] = ffma2(d, w.x, acc[l][0]);
                    acc[l][1] = ffma2(d, w.y, acc[l][1]);
                }
            }
        }
#pragma unroll
        for (int l = 0; l < 4; l++) {
            float2 r0 = relu2(acc[l][0]), r1 = relu2(acc[l][1]);
            st4(A + 1664 + rgt * 272 + l * 64 + jg4, make_float4(r0.x, r0.y, r1.x, r1.y));
        }
    }
    __syncwarp();

    // ---- S3: QKV ----
#pragma unroll
    for (int m = 0; m < 3; m++) {
        ulonglong2 bm = ld128(attn_in_b + 64 * m + jg4);
        u64 acc[4][2];
#pragma unroll
        for (int l = 0; l < 4; l++) { acc[l][0] = bm.x; acc[l][1] = bm.y; }
#pragma unroll 2
        for (int k = 0; k < 64; k += 4) {
            float ev[4][4];
#pragma unroll
            for (int l = 0; l < 4; l++) {
                float4 v = ld4(A + 1664 + rgt * 272 + l * 64 + k);
                ev[l][0] = v.x; ev[l][1] = v.y; ev[l][2] = v.z; ev[l][3] = v.w;
            }
#pragma unroll
            for (int kk = 0; kk < 4; kk++) {
                ulonglong2 w = ld128(attn_in_w + (k + kk) * 192 + 64 * m + jg4);
#pragma unroll
                for (int l = 0; l < 4; l++) {
                    u64 d = dup2(ev[l][kk]);
                    acc[l][0] = ffma2(d, w.x, acc[l][0]);
                    acc[l][1] = ffma2(d, w.y, acc[l][1]);
                }
            }
        }
#pragma unroll
        for (int l = 0; l < 4; l++) {
            float a0, a1, a2, a3; upk2(acc[l][0], a0, a1); upk2(acc[l][1], a2, a3);
            st4(A + rgt * 816 + l * 200 + m * 64 + jg4, make_float4(a0, a1, a2, a3));
        }
    }
    __syncwarp();

    // ---- S4: attention ----
    {
        const int t4 = rgt, r4 = lane & 15, hh = r4 >> 2, ql = r4 & 3;
        const float* qb = A + t4 * 816 + ql * 200 + hh * 16;
        float q[16];
#pragma unroll
        for (int i = 0; i < 4; i++) {
            float4 v = ld4(qb + 4 * i);
            q[4*i] = v.x; q[4*i+1] = v.y; q[4*i+2] = v.z; q[4*i+3] = v.w;
        }
        float sc[4];
#pragma unroll
        for (int kl = 0; kl < 4; kl++) {
            const float* kb = A + t4 * 816 + kl * 200 + 64 + hh * 16;
            float d = 0.f;
#pragma unroll
            for (int i = 0; i < 4; i++) {
                float4 v = ld4(kb + 4 * i);
                d = fmaf(q[4*i], v.x, d); d = fmaf(q[4*i+1], v.y, d);
                d = fmaf(q[4*i+2], v.z, d); d = fmaf(q[4*i+3], v.w, d);
            }
            sc[kl] = d * 0.25f;
        }
        float mx = fmaxf(fmaxf(sc[0], sc[1]), fmaxf(sc[2], sc[3]));
        float es = 0.f;
#pragma unroll
        for (int kl = 0; kl < 4; kl++) { sc[kl] = __expf(sc[kl] - mx); es += sc[kl]; }
        float inv = 1.f / es;
#pragma unroll
        for (int kl = 0; kl < 4; kl++) sc[kl] *= inv;
        float o[16];
#pragma unroll
        for (int i = 0; i < 4; i++) {
            float ox = 0.f, oy = 0.f, oz = 0.f, ow = 0.f;
#pragma unroll
            for (int kl = 0; kl < 4; kl++) {
                float4 v = ld4(A + t4 * 816 + kl * 200 + 128 + hh * 16 + 4 * i);
                ox = fmaf(sc[kl], v.x, ox); oy = fmaf(sc[kl], v.y, oy);
                oz = fmaf(sc[kl], v.z, oz); ow = fmaf(sc[kl], v.w, ow);
            }
            o[4*i] = ox; o[4*i+1] = oy; o[4*i+2] = oz; o[4*i+3] = ow;
        }
        __syncwarp();
#pragma unroll
        for (int i = 0; i < 4; i++)
            st4(A + t4 * 280 + ql * 68 + hh * 16 + 4 * i,
                make_float4(o[4*i], o[4*i+1], o[4*i+2], o[4*i+3]));
    }
    __syncwarp();

    // ---- S5a: obar ----
#pragma unroll
    for (int ii = 0; ii < 4; ii++) {
        int i = lane + 32 * ii;
        int t = i >> 6, jj = i & 63;
        float s = A[t*280 + jj] + A[t*280 + 68 + jj] + A[t*280 + 136 + jj] + A[t*280 + 204 + jj];
        A[1088 + t * 80 + jj] = 0.25f * s;
    }
    __syncthreads();   // o reads done block-wide before phS overwrites wb[0]

    // ---- S5b: ctx -> featp[0:64) ----
    {
        ulonglong2 ob = ld128(attn_out_b + jg4);
        u64 a0 = ob.x, a1 = ob.y;
#pragma unroll 2
        for (int k = 0; k < 64; k += 4) {
            float4 v = ld4(A + 1088 + rgt * 80 + k);
            float ov[4] = {v.x, v.y, v.z, v.w};
#pragma unroll
            for (int kk = 0; kk < 4; kk++) {
                ulonglong2 w = ld128(attn_out_w + (k + kk) * 64 + jg4);
                u64 d = dup2(ov[kk]);
                a0 = ffma2(d, w.x, a0);
                a1 = ffma2(d, w.y, a1);
            }
        }
        const int row = warp * 2 + rgt;
        float c0, c1, c2, c3; upk2(a0, c0, c1); upk2(a1, c2, c3);
        featp[jg4 + 0][row] = c0; featp[jg4 + 1][row] = c1;
        featp[jg4 + 2][row] = c2; featp[jg4 + 3][row] = c3;
    }

    // ---- S6 L1: phase hidden -> phS[row][k] (block-shared) ----
    {
        ulonglong2 PB = ld128(phase_b1 + j4);
        ulonglong2 PW[5];
#pragma unroll
        for (int k = 0; k < 5; k++) PW[k] = ld128(phase_w1 + k * 128 + j4);
#pragma unroll
        for (int t = 0; t < 2; t++) {
            const int n = t ? nb : na;
            float4 po = ld4(phase_onehot + 4 * n);
            float x[5] = {po.x, po.y, po.z, po.w, ee[t]};
            u64 lo = PB.x, hi = PB.y;
#pragma unroll
            for (int k = 0; k < 5; k++) {
                u64 d = dup2(x[k]);
                lo = ffma2(d, PW[k].x, lo);
                hi = ffma2(d, PW[k].y, hi);
            }
            float2 r0 = relu2(lo), r1 = relu2(hi);
            st4(phS + (2 * warp + t) * 132 + j4, make_float4(r0.x, r0.y, r1.x, r1.y));
        }
    }
    __syncthreads();   // phS complete

    // ---- S6 L2 partial: quadrant coop (k-half x row-half), out Pp[kh][row][j] ----
    {
        const int kh = warp & 1, rh = warp >> 1;
        const int k0 = 64 * kh, r0 = 4 * rh;
        float* Pp = kh ? Pp1 : Pp0;
        u64 acc[4][2];
#pragma unroll
        for (int r = 0; r < 4; r++) acc[r][0] = acc[r][1] = 0ULL;
        for (int k = k0; k < k0 + 64; k += 4) {
            float av[4][4];
#pragma unroll
            for (int r = 0; r < 4; r++) {
                float4 v = ld4(phS + (r0 + r) * 132 + k);
                av[r][0] = v.x; av[r][1] = v.y; av[r][2] = v.z; av[r][3] = v.w;
            }
#pragma unroll
            for (int kk = 0; kk < 4; kk++) {
                ulonglong2 w = ld128(phase_w2 + (k + kk) * 128 + j4);
#pragma unroll
                for (int r = 0; r < 4; r++) {
                    u64 d = dup2(av[r][kk]);
                    acc[r][0] = ffma2(d, w.x, acc[r][0]);
                    acc[r][1] = ffma2(d, w.y, acc[r][1]);
                }
            }
        }
#pragma unroll
        for (int r = 0; r < 4; r++) {
            float a0, a1, a2, a3; upk2(acc[r][0], a0, a1); upk2(acc[r][1], a2, a3);
            st4(Pp + (r0 + r) * 128 + j4, make_float4(a0, a1, a2, a3));
        }
    }
    __syncthreads();

    // ---- S6 L2 final: reduce halves + bias + relu -> featp[64:192) ; S7 region ----
    {
        float4 b = ld4(phase_b2 + j4);
#pragma unroll
        for (int rr = 0; rr < 2; rr++) {
            const int r = 2 * warp + rr;
            float4 p0 = ld4(Pp0 + r * 128 + j4);
            float4 p1 = ld4(Pp1 + r * 128 + j4);
            featp[64 + j4 + 0][r] = relu(p0.x + p1.x + b.x);
            featp[64 + j4 + 1][r] = relu(p0.y + p1.y + b.y);
            featp[64 + j4 + 2][r] = relu(p0.z + p1.z + b.z);
            featp[64 + j4 + 3][r] = relu(p0.w + p1.w + b.w);
        }
    }
    if (lane < 16) {
        const int t = lane >> 3, f = lane & 7;
        const int n = t ? nb : na;
        int rid = region_ids[n];
        rid = min(max(rid, 0), 3);
        featp[192 + f][warp * 2 + t] = region_table[rid * 8 + f];
    }
    __syncthreads();

    // ---- S8: head GEMM, thread owns j=tid, rows packed in f32x2 ----
    {
        const int j = tid;
        u64 acc8[4];
        u64 bj = dup2(head_b1[j]);
#pragma unroll
        for (int r = 0; r < 4; r++) acc8[r] = bj;
#pragma unroll 8
        for (int k = 0; k < 200; k++) {
            u64 wk = dup2(head_w1[k * 128 + j]);
            ulonglong2 fa = ld128(&featp[k][0]);
            ulonglong2 fb = ld128(&featp[k][4]);
            acc8[0] = ffma2(fa.x, wk, acc8[0]);
            acc8[1] = ffma2(fa.y, wk, acc8[1]);
            acc8[2] = ffma2(fb.x, wk, acc8[2]);
            acc8[3] = ffma2(fb.y, wk, acc8[3]);
        }
        const float w2j = head_w2[j];
        u64 s[4];
#pragma unroll
        for (int r = 0; r < 4; r++) {
            float2 a = relu2(acc8[r]);
            s[r] = pk2(a.x * w2j, a.y * w2j);
        }
#pragma unroll
        for (int off = 16; off > 0; off >>= 1) {
#pragma unroll
            for (int r = 0; r < 4; r++)
                s[r] = add2(s[r], __shfl_xor_sync(0xffffffffu, s[r], off));
        }
        if (lane == 0) {
#pragma unroll
            for (int r = 0; r < 4; r++) {
                float a, b; upk2(s[r], a, b);
                partial[warp][2 * r] = a; partial[warp][2 * r + 1] = b;
            }
        }
    }
    __syncthreads();

    if (warp == 0 && lane < 8) {
        const int row = lane;
        const int n = blockIdx.x * TLB + row;
        if (n < N) {
            float mean = partial[0][row] + partial[1][row] + partial[2][row] + partial[3][row]
                       + head_b2[0];
            float ls = log_std[0];
            float sd = expf(ls);
            float nz = noise[n];
            float act = mean + sd * nz;
            out[n] = fminf(fmaxf(act, -1.0f), 1.0f);
            out[N + n] = -0.5f * (nz * nz + 2.0f * ls + 1.8378770664093454f);
        }
    }
}

extern "C" void kernel_launch(void* const* d_in, const int* in_sizes, int n_in,
                              void* d_out, int out_size)
{
    const float* queue        = (const float*)d_in[0];
    const float* waiting      = (const float*)d_in[1];
    const float* phase_onehot = (const float*)d_in[2];
    const float* elapsed      = (const float*)d_in[3];
    const int*   region_ids   = (const int*)  d_in[4];
    const float* noise        = (const float*)d_in[5];
    const float* lane_w1      = (const float*)d_in[6];
    const float* lane_b1      = (const float*)d_in[7];
    const float* lane_w2      = (const float*)d_in[8];
    const float* lane_b2      = (const float*)d_in[9];
    const float* attn_in_w    = (const float*)d_in[10];
    const float* attn_in_b    = (const float*)d_in[11];
    const float* attn_out_w   = (const float*)d_in[12];
    const float* attn_out_b   = (const float*)d_in[13];
    const float* phase_w1     = (const float*)d_in[14];
    const float* phase_b1     = (const float*)d_in[15];
    const float* phase_w2     = (const float*)d_in[16];
    const float* phase_b2     = (const float*)d_in[17];
    const float* region_table = (const float*)d_in[18];
    const float* head_w1      = (const float*)d_in[19];
    const float* head_b1      = (const float*)d_in[20];
    const float* head_w2      = (const float*)d_in[21];
    const float* head_b2      = (const float*)d_in[22];
    const float* log_std      = (const float*)d_in[23];

    const int N = in_sizes[3];
    float* out = (float*)d_out;

    int blocks = (N + TLB - 1) / TLB;
    policy_kernel<<<blocks, NWARP * 32>>>(
        queue, waiting, phase_onehot, elapsed, region_ids, noise,
        lane_w1, lane_b1, lane_w2, lane_b2,
        attn_in_w, attn_in_b, attn_out_w, attn_out_b,
        phase_w1, phase_b1, phase_w2, phase_b2,
        region_table, head_w1, head_b1, head_w2, head_b2, log_std,
        out, N);
}